// round 13
// baseline (speedup 1.0000x reference)
#include <cuda_runtime.h>
#include <cuda_bf16.h>
#include <cstdint>

#define NN 50000
#define DD 128
#define LAYERS 5
#define NVEC4 (NN * DD / 4)
#define NB ((NN + 255) / 256)
#define EMAX 1000000
#define TILES ((NN + 63) / 64)   // 782
#define NBLK 444                 // 3 blocks/SM x 148 SMs

// ---------------- scratch (static device allocations; no cudaMalloc) --------
__device__ float g_rst[NN * DD];
__device__ float g_x1[NN * DD];
__device__ float g_x2[NN * DD];
__device__ float g_stats[6 * DD];
__device__ float g_coef[6 * DD];   // slots 2..5: bn2 (a,c), bn3 (a,c)
__device__ int g_deg[NN];
__device__ int g_rowptr[NN + 1];
__device__ int g_cur[NN];
__device__ int g_eidx[EMAX];
__device__ int g_bsum[NB];
__device__ int g_bscan[NB];
__device__ unsigned short g_Bhi[10 * 16384];
__device__ unsigned short g_Blo[10 * 16384];
__device__ unsigned int g_bar_count = 0;
__device__ volatile unsigned int g_bar_gen = 0;

// ---------------- helpers ----------------------------------------------------
__device__ __forceinline__ uint32_t packbf(__nv_bfloat16 lo16, __nv_bfloat16 hi16) {
    return (uint32_t)__bfloat16_as_ushort(lo16) |
           ((uint32_t)__bfloat16_as_ushort(hi16) << 16);
}

#define MMA_BF16(d0, d1, d2, d3, a0, a1, a2, a3, b0, b1) \
    asm volatile("mma.sync.aligned.m16n8k16.row.col.f32.bf16.bf16.f32 " \
                 "{%0,%1,%2,%3}, {%4,%5,%6,%7}, {%8,%9}, {%0,%1,%2,%3};" \
                 : "+f"(d0), "+f"(d1), "+f"(d2), "+f"(d3) \
                 : "r"(a0), "r"(a1), "r"(a2), "r"(a3), "r"(b0), "r"(b1))

__device__ __forceinline__ void grid_barrier() {
    __syncthreads();
    if (threadIdx.x == 0) {
        unsigned int old = g_bar_gen;
        __threadfence();
        unsigned int a = atomicAdd(&g_bar_count, 1u);
        if (a == NBLK - 1) {
            atomicExch(&g_bar_count, 0u);
            __threadfence();
            g_bar_gen = old + 1;
        } else {
            while (g_bar_gen == old) __nanosleep(128);
        }
        __threadfence();
    }
    __syncthreads();
}

// ---------------- CSR build --------------------------------------------------
__global__ void zero_deg_kernel(int* __restrict__ deg) {
    int i = blockIdx.x * 256 + threadIdx.x;
    if (i < NN) deg[i] = 0;
}
__global__ void count_deg_kernel(const int* __restrict__ dst, int* __restrict__ deg, int E) {
    int e = blockIdx.x * 256 + threadIdx.x;
    if (e < E) atomicAdd(&deg[dst[e]], 1);
}
__global__ void scanA_kernel(const int* __restrict__ deg, int* __restrict__ rowptr,
                             int* __restrict__ bsum) {
    __shared__ int ssc[256];
    int tid = threadIdx.x;
    int idx = blockIdx.x * 256 + tid;
    int val = (idx < NN) ? deg[idx] : 0;
    ssc[tid] = val;
    __syncthreads();
#pragma unroll
    for (int off = 1; off < 256; off <<= 1) {
        int t = (tid >= off) ? ssc[tid - off] : 0;
        __syncthreads();
        ssc[tid] += t;
        __syncthreads();
    }
    if (idx < NN) rowptr[idx] = ssc[tid] - val;
    if (tid == 255) bsum[blockIdx.x] = ssc[255];
}
__global__ void scanB_kernel(const int* __restrict__ bsum, int* __restrict__ bscan,
                             int* __restrict__ rowptr) {
    __shared__ int ssc[256];
    int tid = threadIdx.x;
    int val = (tid < NB) ? bsum[tid] : 0;
    ssc[tid] = val;
    __syncthreads();
#pragma unroll
    for (int off = 1; off < 256; off <<= 1) {
        int t = (tid >= off) ? ssc[tid - off] : 0;
        __syncthreads();
        ssc[tid] += t;
        __syncthreads();
    }
    if (tid < NB) bscan[tid] = ssc[tid] - val;
    if (tid == 255) rowptr[NN] = ssc[255];
}
__global__ void scanC_kernel(int* __restrict__ rowptr, const int* __restrict__ bscan,
                             int* __restrict__ cur) {
    int i = blockIdx.x * 256 + threadIdx.x;
    if (i < NN) {
        int v = rowptr[i] + bscan[blockIdx.x];
        rowptr[i] = v;
        cur[i] = v;
    }
}
__global__ void scatter_kernel(const int* __restrict__ src, const int* __restrict__ dst,
                               int* __restrict__ cur, int* __restrict__ eidx, int E) {
    int e = blockIdx.x * 256 + threadIdx.x;
    if (e < E) {
        int p = atomicAdd(&cur[dst[e]], 1);
        eidx[p] = src[e];
    }
}

// pre-convert weights: Bt[n][k] = W[k][n], split into bf16 hi + lo
__global__ void convert_w_kernel(const float* __restrict__ W1, const float* __restrict__ W2,
                                 unsigned short* __restrict__ bhi,
                                 unsigned short* __restrict__ blo) {
    int m = blockIdx.y;
    const float* W = (m < 5) ? (W1 + m * 16384) : (W2 + (m - 5) * 16384);
    int e = blockIdx.x * 256 + threadIdx.x;
    int n = e >> 7, k = e & 127;
    float val = W[k * 128 + n];
    __nv_bfloat16 h = __float2bfloat16(val);
    __nv_bfloat16 l = __float2bfloat16(val - __bfloat162float(h));
    bhi[m * 16384 + n * 128 + k] = __bfloat16_as_ushort(h);
    blo[m * 16384 + n * 128 + k] = __bfloat16_as_ushort(l);
}

// ---------------- smem layout (N-split: B holds 64 cols) ---------------------
#define STRD32 68
#define SM_AHI 0
#define SM_ALO (64 * STRD32 * 4)               // 17408
#define SM_BHI (2 * 64 * STRD32 * 4)           // 34816
#define SM_BLO (SM_BHI + 64 * STRD32 * 4)      // 52224
#define SM_BIAS (SM_BLO + 64 * STRD32 * 4)     // 69632
#define SM_CA (SM_BIAS + 512)
#define SM_CC (SM_CA + 512)
#define SM_STATS (SM_CC + 512)
#define GEMM_SMEM (SM_STATS + 1024)            // 72704 B -> 3 blocks/SM

// GEMM phase: for each N-half, stage W-half once, loop row tiles.
// Column stats accumulated in smem across all tiles, flushed once.
template <bool APPLY_BN>
__device__ __forceinline__ void gemm_phase(
    char* sm, const float* __restrict__ A,
    const unsigned short* __restrict__ Bhi, const unsigned short* __restrict__ Blo,
    const float* __restrict__ bias,
    const float* __restrict__ ssum_in, const float* __restrict__ ssq_in,
    const float* __restrict__ bng, const float* __restrict__ bnb,
    float* __restrict__ out, float* __restrict__ ssum, float* __restrict__ ssq) {
    int tid = threadIdx.x;
    int wid = tid >> 5, lane = tid & 31;

    uint32_t* AHI = (uint32_t*)(sm + SM_AHI);
    uint32_t* ALO = (uint32_t*)(sm + SM_ALO);
    uint32_t* BHI = (uint32_t*)(sm + SM_BHI);
    uint32_t* BLO = (uint32_t*)(sm + SM_BLO);
    float* sums = (float*)(sm + SM_STATS);
    float* sqs = sums + 128;

    if (tid < 128) {
        ((float*)(sm + SM_BIAS))[tid] = bias[tid];
        sums[tid] = 0.f;
        sqs[tid] = 0.f;
        if (APPLY_BN) {
            float m = ssum_in[tid] * (1.0f / NN);
            float var = ssq_in[tid] * (1.0f / NN) - m * m;
            float a = bng[tid] * rsqrtf(var + 1e-5f);
            ((float*)(sm + SM_CA))[tid] = a;
            ((float*)(sm + SM_CC))[tid] = bnb[tid] - m * a;
        }
    }

    for (int half = 0; half < 2; half++) {
        // stage this W half (rows half*64 .. half*64+63 of Bt)
        {
            const uint32_t* s0 = (const uint32_t*)(Bhi + half * 64 * 128);
            const uint32_t* s1 = (const uint32_t*)(Blo + half * 64 * 128);
#pragma unroll 4
            for (int i = tid; i < 4096; i += 256) {
                int r = i >> 6, kc = i & 63;
                BHI[r * STRD32 + kc] = s0[i];
                BLO[r * STRD32 + kc] = s1[i];
            }
        }
        __syncthreads();

        for (int tile = blockIdx.x; tile < TILES; tile += NBLK) {
            int brow0 = tile * 64;
            // stage act(A) as bf16 hi/lo (full K=128)
            {
                int row = tid >> 2;
                int q = tid & 3;
                int grow = brow0 + row;
                bool valid = grow < NN;
                const float4* ap = (const float4*)(A + (size_t)grow * DD);
                const float* caS = (const float*)(sm + SM_CA);
                const float* ccS = (const float*)(sm + SM_CC);
                uint32_t* ahi = AHI + row * STRD32;
                uint32_t* alo = ALO + row * STRD32;
#pragma unroll
                for (int i = 0; i < 8; i++) {
                    int v = q + 4 * i;
                    float4 x = valid ? ap[v] : make_float4(0.f, 0.f, 0.f, 0.f);
                    if (APPLY_BN) {
                        int k0 = v * 4;
                        x.x = fmaxf(fmaf(x.x, caS[k0 + 0], ccS[k0 + 0]), 0.f);
                        x.y = fmaxf(fmaf(x.y, caS[k0 + 1], ccS[k0 + 1]), 0.f);
                        x.z = fmaxf(fmaf(x.z, caS[k0 + 2], ccS[k0 + 2]), 0.f);
                        x.w = fmaxf(fmaf(x.w, caS[k0 + 3], ccS[k0 + 3]), 0.f);
                    }
                    __nv_bfloat16 hx = __float2bfloat16(x.x);
                    __nv_bfloat16 hy = __float2bfloat16(x.y);
                    __nv_bfloat16 hz = __float2bfloat16(x.z);
                    __nv_bfloat16 hw = __float2bfloat16(x.w);
                    ahi[v * 2 + 0] = packbf(hx, hy);
                    ahi[v * 2 + 1] = packbf(hz, hw);
                    alo[v * 2 + 0] = packbf(__float2bfloat16(x.x - __bfloat162float(hx)),
                                            __float2bfloat16(x.y - __bfloat162float(hy)));
                    alo[v * 2 + 1] = packbf(__float2bfloat16(x.z - __bfloat162float(hz)),
                                            __float2bfloat16(x.w - __bfloat162float(hw)));
                }
            }
            __syncthreads();

            // MMA: warps = 4 row-groups x 2 col-groups (32 cols each)
            int row0w = (wid & 3) * 16;
            int col0w = (wid >> 2) * 32;
            int g = lane >> 2, t = lane & 3;

            const uint32_t* Ah0p = AHI + (row0w + g) * STRD32 + t;
            const uint32_t* Ah1p = AHI + (row0w + 8 + g) * STRD32 + t;
            const uint32_t* Al0p = ALO + (row0w + g) * STRD32 + t;
            const uint32_t* Al1p = ALO + (row0w + 8 + g) * STRD32 + t;
            const uint32_t* Bhp = BHI + (col0w + g) * STRD32 + t;
            const uint32_t* Blp = BLO + (col0w + g) * STRD32 + t;

            float acc[4][4];
#pragma unroll
            for (int i = 0; i < 4; i++)
#pragma unroll
                for (int j = 0; j < 4; j++) acc[i][j] = 0.f;

#pragma unroll
            for (int ks = 0; ks < 8; ks++) {
                int ko = ks * 8;
                uint32_t ah0 = Ah0p[ko], ah1 = Ah1p[ko];
                uint32_t ah2 = Ah0p[ko + 4], ah3 = Ah1p[ko + 4];
                uint32_t al0 = Al0p[ko], al1 = Al1p[ko];
                uint32_t al2 = Al0p[ko + 4], al3 = Al1p[ko + 4];
#pragma unroll
                for (int nf = 0; nf < 4; nf++) {
                    int bo = ko + nf * 8 * STRD32;
                    uint32_t bh0 = Bhp[bo], bh1 = Bhp[bo + 4];
                    uint32_t bl0 = Blp[bo], bl1 = Blp[bo + 4];
                    MMA_BF16(acc[nf][0], acc[nf][1], acc[nf][2], acc[nf][3],
                             ah0, ah1, ah2, ah3, bh0, bh1);
                    MMA_BF16(acc[nf][0], acc[nf][1], acc[nf][2], acc[nf][3],
                             ah0, ah1, ah2, ah3, bl0, bl1);
                    MMA_BF16(acc[nf][0], acc[nf][1], acc[nf][2], acc[nf][3],
                             al0, al1, al2, al3, bh0, bh1);
                }
            }

            // epilogue: + bias, store, column stats (cols in this half)
            {
                int grow0 = brow0 + row0w + g;
                int grow1 = grow0 + 8;
                bool ok0 = grow0 < NN, ok1 = grow1 < NN;
                const float* bS = (const float*)(sm + SM_BIAS);
#pragma unroll
                for (int nf = 0; nf < 4; nf++) {
                    int c = half * 64 + col0w + nf * 8 + 2 * t;
                    float bx = bS[c], by = bS[c + 1];
                    float a0 = acc[nf][0] + bx, a1 = acc[nf][1] + by;
                    float a2 = acc[nf][2] + bx, a3 = acc[nf][3] + by;
                    if (ok0)
                        *(float2*)(out + (size_t)grow0 * DD + c) = make_float2(a0, a1);
                    if (ok1)
                        *(float2*)(out + (size_t)grow1 * DD + c) = make_float2(a2, a3);
                    float s0 = (ok0 ? a0 : 0.f) + (ok1 ? a2 : 0.f);
                    float s1 = (ok0 ? a1 : 0.f) + (ok1 ? a3 : 0.f);
                    float q0 = (ok0 ? a0 * a0 : 0.f) + (ok1 ? a2 * a2 : 0.f);
                    float q1 = (ok0 ? a1 * a1 : 0.f) + (ok1 ? a3 * a3 : 0.f);
#pragma unroll
                    for (int m = 16; m >= 4; m >>= 1) {
                        s0 += __shfl_xor_sync(0xffffffffu, s0, m);
                        s1 += __shfl_xor_sync(0xffffffffu, s1, m);
                        q0 += __shfl_xor_sync(0xffffffffu, q0, m);
                        q1 += __shfl_xor_sync(0xffffffffu, q1, m);
                    }
                    if (lane < 4) {
                        atomicAdd(&sums[c], s0);
                        atomicAdd(&sums[c + 1], s1);
                        atomicAdd(&sqs[c], q0);
                        atomicAdd(&sqs[c + 1], q1);
                    }
                }
            }
            __syncthreads();
        }
        __syncthreads();  // done with this half's B before restaging
    }
    if (tid < 128) {
        atomicAdd(ssum + tid, sums[tid]);
        atomicAdd(ssq + tid, sqs[tid]);
    }
}

// ---------------- persistent mega kernel -------------------------------------
__global__ void __launch_bounds__(256, 3)
gin_mega_kernel(const float* __restrict__ h_in,
                const int* __restrict__ eidx, const int* __restrict__ rowptr,
                const unsigned short* __restrict__ BhiAll,
                const unsigned short* __restrict__ BloAll,
                const float* __restrict__ b1, const float* __restrict__ b2,
                const float* __restrict__ bn1g, const float* __restrict__ bn1b,
                const float* __restrict__ bn2g, const float* __restrict__ bn2b,
                const float* __restrict__ bn3g, const float* __restrict__ bn3b,
                float* __restrict__ rst, float* __restrict__ x1,
                float* __restrict__ x2, float* __restrict__ stats,
                float* __restrict__ coef, float* __restrict__ outp) {
    extern __shared__ char sm[];
    int tid = threadIdx.x;
    int bid = blockIdx.x;
    int wid = tid >> 5, lane = tid & 31;

    for (int l = 0; l < LAYERS; l++) {
        // ---- Phase A: aggregation (bn2->bn3 chain fused for l>0) ----
        {
            float4 A2, C2, A3, C3;
            bool ap = (l > 0);
            if (ap) {
                A2 = ((const float4*)(coef + 2 * DD))[lane];
                C2 = ((const float4*)(coef + 3 * DD))[lane];
                A3 = ((const float4*)(coef + 4 * DD))[lane];
                C3 = ((const float4*)(coef + 5 * DD))[lane];
            }
            const float4* xp = (const float4*)((l == 0) ? h_in : x2);
            auto f = [&](float4 v) -> float4 {
                if (ap) {
                    v.x = fmaxf(fmaf(fmaxf(fmaf(v.x, A2.x, C2.x), 0.f), A3.x, C3.x), 0.f);
                    v.y = fmaxf(fmaf(fmaxf(fmaf(v.y, A2.y, C2.y), 0.f), A3.y, C3.y), 0.f);
                    v.z = fmaxf(fmaf(fmaxf(fmaf(v.z, A2.z, C2.z), 0.f), A3.z, C3.z), 0.f);
                    v.w = fmaxf(fmaf(fmaxf(fmaf(v.w, A2.w, C2.w), 0.f), A3.w, C3.w), 0.f);
                }
                return v;
            };
            for (int node = bid * 8 + wid; node < NN; node += NBLK * 8) {
                int s = rowptr[node], e = rowptr[node + 1];
                float4 acc = f(xp[(size_t)node * 32 + lane]);
                int i = s;
                for (; i + 8 <= e; i += 8) {
                    int jj[8];
#pragma unroll
                    for (int u = 0; u < 8; u++) jj[u] = eidx[i + u];
                    float4 v[8];
#pragma unroll
                    for (int u = 0; u < 8; u++) v[u] = xp[(size_t)jj[u] * 32 + lane];
#pragma unroll
                    for (int u = 0; u < 8; u++) {
                        float4 t = f(v[u]);
                        acc.x += t.x; acc.y += t.y; acc.z += t.z; acc.w += t.w;
                    }
                }
                for (; i < e; i++) {
                    float4 t = f(xp[(size_t)eidx[i] * 32 + lane]);
                    acc.x += t.x; acc.y += t.y; acc.z += t.z; acc.w += t.w;
                }
                ((float4*)rst)[(size_t)node * 32 + lane] = acc;
            }
        }
        grid_barrier();

        // ---- Phase B: x1 = rst @ W1 + b1 (+stats1) ----
        gemm_phase<false>(sm, rst, BhiAll + l * 16384, BloAll + l * 16384, b1 + l * DD,
                          nullptr, nullptr, nullptr, nullptr,
                          x1, stats + 0 * DD, stats + 1 * DD);
        grid_barrier();

        // ---- Phase C: x2 = relu(bn1(x1)) @ W2 + b2 (+stats2) ----
        gemm_phase<true>(sm, x1, BhiAll + (5 + l) * 16384, BloAll + (5 + l) * 16384,
                         b2 + l * DD, stats + 0 * DD, stats + 1 * DD,
                         bn1g + l * DD, bn1b + l * DD,
                         x2, stats + 2 * DD, stats + 3 * DD);
        grid_barrier();

        // ---- Phase D: stats of y = relu(bn2(x2)); publish coef2 ----
        {
            float* caS = (float*)(sm + SM_CA);
            float* ccS = (float*)(sm + SM_CC);
            float4* ss = (float4*)(sm + SM_AHI);        // [8][32]
            float4* sq = ss + 256;                      // [8][32]
            if (tid < 128) {
                float m = stats[2 * DD + tid] * (1.0f / NN);
                float var = stats[3 * DD + tid] * (1.0f / NN) - m * m;
                float a = bn2g[l * DD + tid] * rsqrtf(var + 1e-5f);
                float cc = bn2b[l * DD + tid] - m * a;
                caS[tid] = a;
                ccS[tid] = cc;
                if (bid == 0) {
                    coef[2 * DD + tid] = a;
                    coef[3 * DD + tid] = cc;
                }
            }
            __syncthreads();
            int c4 = tid & 31, rg = tid >> 5;
            float4 a = ((const float4*)caS)[c4];
            float4 off = ((const float4*)ccS)[c4];
            float4 s = make_float4(0.f, 0.f, 0.f, 0.f);
            float4 q = make_float4(0.f, 0.f, 0.f, 0.f);
            for (int tile = bid; tile < TILES; tile += NBLK) {
                int r0 = tile * 64 + rg * 8;
#pragma unroll
                for (int i = 0; i < 8; i++) {
                    int r = r0 + i;
                    if (r < NN) {
                        float4 v = ((const float4*)(x2 + (size_t)r * DD))[c4];
                        v.x = fmaxf(fmaf(v.x, a.x, off.x), 0.f);
                        v.y = fmaxf(fmaf(v.y, a.y, off.y), 0.f);
                        v.z = fmaxf(fmaf(v.z, a.z, off.z), 0.f);
                        v.w = fmaxf(fmaf(v.w, a.w, off.w), 0.f);
                        s.x += v.x; s.y += v.y; s.z += v.z; s.w += v.w;
                        q.x += v.x * v.x; q.y += v.y * v.y;
                        q.z += v.z * v.z; q.w += v.w * v.w;
                    }
                }
            }
            ss[rg * 32 + c4] = s;
            sq[rg * 32 + c4] = q;
            __syncthreads();
            if (rg == 0) {
                float4 S = ss[c4], Q = sq[c4];
#pragma unroll
                for (int r = 1; r < 8; r++) {
                    float4 t1 = ss[r * 32 + c4], t2 = sq[r * 32 + c4];
                    S.x += t1.x; S.y += t1.y; S.z += t1.z; S.w += t1.w;
                    Q.x += t2.x; Q.y += t2.y; Q.z += t2.z; Q.w += t2.w;
                }
                int c = c4 * 4;
                atomicAdd(stats + 4 * DD + c + 0, S.x);
                atomicAdd(stats + 4 * DD + c + 1, S.y);
                atomicAdd(stats + 4 * DD + c + 2, S.z);
                atomicAdd(stats + 4 * DD + c + 3, S.w);
                atomicAdd(stats + 5 * DD + c + 0, Q.x);
                atomicAdd(stats + 5 * DD + c + 1, Q.y);
                atomicAdd(stats + 5 * DD + c + 2, Q.z);
                atomicAdd(stats + 5 * DD + c + 3, Q.w);
            }
        }
        grid_barrier();

        // ---- Phase E: bn3 coefs; zero all stats for next layer ----
        if (bid == 0 && tid < 128) {
            float m = stats[4 * DD + tid] * (1.0f / NN);
            float var = stats[5 * DD + tid] * (1.0f / NN) - m * m;
            float a = bn3g[l * DD + tid] * rsqrtf(var + 1e-5f);
            coef[4 * DD + tid] = a;
            coef[5 * DD + tid] = bn3b[l * DD + tid] - m * a;
#pragma unroll
            for (int s2 = 0; s2 < 6; s2++) stats[s2 * DD + tid] = 0.f;
        }
        grid_barrier();
    }

    // ---- Phase F: out = relu(bn3(relu(bn2(x2)))) ----
    for (int idx = bid * 256 + tid; idx < NVEC4; idx += NBLK * 256) {
        float4 v = ((const float4*)x2)[idx];
        int c0 = (idx * 4) & (DD - 1);
        v.x = fmaxf(fmaf(v.x, coef[2 * DD + c0 + 0], coef[3 * DD + c0 + 0]), 0.f);
        v.y = fmaxf(fmaf(v.y, coef[2 * DD + c0 + 1], coef[3 * DD + c0 + 1]), 0.f);
        v.z = fmaxf(fmaf(v.z, coef[2 * DD + c0 + 2], coef[3 * DD + c0 + 2]), 0.f);
        v.w = fmaxf(fmaf(v.w, coef[2 * DD + c0 + 3], coef[3 * DD + c0 + 3]), 0.f);
        v.x = fmaxf(fmaf(v.x, coef[4 * DD + c0 + 0], coef[5 * DD + c0 + 0]), 0.f);
        v.y = fmaxf(fmaf(v.y, coef[4 * DD + c0 + 1], coef[5 * DD + c0 + 1]), 0.f);
        v.z = fmaxf(fmaf(v.z, coef[4 * DD + c0 + 2], coef[5 * DD + c0 + 2]), 0.f);
        v.w = fmaxf(fmaf(v.w, coef[4 * DD + c0 + 3], coef[5 * DD + c0 + 3]), 0.f);
        ((float4*)outp)[idx] = v;
    }
}

// ---------------- launch ----------------------------------------------------
extern "C" void kernel_launch(void* const* d_in, const int* in_sizes, int n_in,
                              void* d_out, int out_size) {
    const float* h_in = (const float*)d_in[0];
    const int* src = (const int*)d_in[1];
    const int* dst = (const int*)d_in[2];
    const float* W1 = (const float*)d_in[3];
    const float* b1 = (const float*)d_in[4];
    const float* W2 = (const float*)d_in[5];
    const float* b2 = (const float*)d_in[6];
    const float* bn1g = (const float*)d_in[7];
    const float* bn1b = (const float*)d_in[8];
    const float* bn2g = (const float*)d_in[9];
    const float* bn2b = (const float*)d_in[10];
    const float* bn3g = (const float*)d_in[11];
    const float* bn3b = (const float*)d_in[12];
    int E = in_sizes[1];
    if (E > EMAX) E = EMAX;

    float *rst, *x1, *x2, *stats, *coef;
    unsigned short *bhi, *blo;
    int *deg, *rowptr, *cur, *eidx, *bsum, *bscan;
    cudaGetSymbolAddress((void**)&rst, g_rst);
    cudaGetSymbolAddress((void**)&x1, g_x1);
    cudaGetSymbolAddress((void**)&x2, g_x2);
    cudaGetSymbolAddress((void**)&stats, g_stats);
    cudaGetSymbolAddress((void**)&coef, g_coef);
    cudaGetSymbolAddress((void**)&bhi, g_Bhi);
    cudaGetSymbolAddress((void**)&blo, g_Blo);
    cudaGetSymbolAddress((void**)&deg, g_deg);
    cudaGetSymbolAddress((void**)&rowptr, g_rowptr);
    cudaGetSymbolAddress((void**)&cur, g_cur);
    cudaGetSymbolAddress((void**)&eidx, g_eidx);
    cudaGetSymbolAddress((void**)&bsum, g_bsum);
    cudaGetSymbolAddress((void**)&bscan, g_bscan);

    cudaFuncSetAttribute((const void*)gin_mega_kernel,
                         cudaFuncAttributeMaxDynamicSharedMemorySize, GEMM_SMEM);

    const int e_blocks = (E + 255) / 256;

    // ---- setup: weight conversion + CSR build ----
    convert_w_kernel<<<dim3(64, 10), 256>>>(W1, W2, bhi, blo);
    zero_deg_kernel<<<NB, 256>>>(deg);
    count_deg_kernel<<<e_blocks, 256>>>(dst, deg, E);
    scanA_kernel<<<NB, 256>>>(deg, rowptr, bsum);
    scanB_kernel<<<1, 256>>>(bsum, bscan, rowptr);
    scanC_kernel<<<NB, 256>>>(rowptr, bscan, cur);
    scatter_kernel<<<e_blocks, 256>>>(src, dst, cur, eidx, E);

    // ---- one persistent kernel for all 5 layers + output ----
    gin_mega_kernel<<<NBLK, 256, GEMM_SMEM>>>(
        h_in, eidx, rowptr, bhi, blo, b1, b2,
        bn1g, bn1b, bn2g, bn2b, bn3g, bn3b,
        rst, x1, x2, stats, coef, (float*)d_out);
}

// round 14
// speedup vs baseline: 1.1672x; 1.1672x over previous
#include <cuda_runtime.h>
#include <cuda_bf16.h>
#include <cstdint>

#define NN 50000
#define DD 128
#define LAYERS 5
#define NVEC4 (NN * DD / 4)
#define NB ((NN + 255) / 256)          // 196 scan blocks
#define EMAX 1000000

// ---------------- scratch (static device allocations; no cudaMalloc) --------
__device__ float g_rst[NN * DD];
__device__ float g_x1[NN * DD];
__device__ float g_x2[NN * DD];
__device__ float g_stats[6 * DD];
__device__ float g_coef[6 * DD];
__device__ int g_deg[NN];
__device__ int g_rowptr[NN + 1];
__device__ int g_cur[NN];
__device__ int g_eidx[EMAX];
__device__ int g_bsum[NB];
__device__ int g_bscan[NB];
// pre-converted weights: 10 matrices (5x W1, 5x W2), Bt[n][k] = W[k][n], bf16 hi/lo
__device__ unsigned short g_Bhi[10 * 16384];
__device__ unsigned short g_Blo[10 * 16384];

// ---------------- helpers ----------------------------------------------------
__device__ __forceinline__ uint32_t packbf(__nv_bfloat16 lo16, __nv_bfloat16 hi16) {
    return (uint32_t)__bfloat16_as_ushort(lo16) |
           ((uint32_t)__bfloat16_as_ushort(hi16) << 16);
}

#define MMA_BF16(d0, d1, d2, d3, a0, a1, a2, a3, b0, b1) \
    asm volatile("mma.sync.aligned.m16n8k16.row.col.f32.bf16.bf16.f32 " \
                 "{%0,%1,%2,%3}, {%4,%5,%6,%7}, {%8,%9}, {%0,%1,%2,%3};" \
                 : "+f"(d0), "+f"(d1), "+f"(d2), "+f"(d3) \
                 : "r"(a0), "r"(a1), "r"(a2), "r"(a3), "r"(b0), "r"(b1))

// ---------------- CSR build --------------------------------------------------
__global__ void zero_deg_kernel(int* __restrict__ deg) {
    int i = blockIdx.x * 256 + threadIdx.x;
    if (i < NN) deg[i] = 0;
}
__global__ void count_deg_kernel(const int* __restrict__ dst, int* __restrict__ deg, int E) {
    int e = blockIdx.x * 256 + threadIdx.x;
    if (e < E) atomicAdd(&deg[dst[e]], 1);
}
__global__ void scanA_kernel(const int* __restrict__ deg, int* __restrict__ rowptr,
                             int* __restrict__ bsum) {
    __shared__ int ssc[256];
    int tid = threadIdx.x;
    int idx = blockIdx.x * 256 + tid;
    int val = (idx < NN) ? deg[idx] : 0;
    ssc[tid] = val;
    __syncthreads();
#pragma unroll
    for (int off = 1; off < 256; off <<= 1) {
        int t = (tid >= off) ? ssc[tid - off] : 0;
        __syncthreads();
        ssc[tid] += t;
        __syncthreads();
    }
    if (idx < NN) rowptr[idx] = ssc[tid] - val;  // exclusive
    if (tid == 255) bsum[blockIdx.x] = ssc[255];
}
__global__ void scanB_kernel(const int* __restrict__ bsum, int* __restrict__ bscan,
                             int* __restrict__ rowptr) {
    __shared__ int ssc[256];
    int tid = threadIdx.x;
    int val = (tid < NB) ? bsum[tid] : 0;
    ssc[tid] = val;
    __syncthreads();
#pragma unroll
    for (int off = 1; off < 256; off <<= 1) {
        int t = (tid >= off) ? ssc[tid - off] : 0;
        __syncthreads();
        ssc[tid] += t;
        __syncthreads();
    }
    if (tid < NB) bscan[tid] = ssc[tid] - val;  // exclusive
    if (tid == 255) rowptr[NN] = ssc[255];
}
__global__ void scanC_kernel(int* __restrict__ rowptr, const int* __restrict__ bscan,
                             int* __restrict__ cur) {
    int i = blockIdx.x * 256 + threadIdx.x;
    if (i < NN) {
        int v = rowptr[i] + bscan[blockIdx.x];
        rowptr[i] = v;
        cur[i] = v;
    }
}
__global__ void scatter_kernel(const int* __restrict__ src, const int* __restrict__ dst,
                               int* __restrict__ cur, int* __restrict__ eidx, int E) {
    int e = blockIdx.x * 256 + threadIdx.x;
    if (e < E) {
        int p = atomicAdd(&cur[dst[e]], 1);
        eidx[p] = src[e];
    }
}

// ---------------- aggregation ------------------------------------------------
// rst[i] = f(x[i]) + sum_{j in adj(i)} f(x[j])
// APPLY_F: f(v) = relu(a3*relu(a2*v + c2) + c3) applied elementwise (per column)
// otherwise f = identity.
template <bool APPLY_F>
__global__ void __launch_bounds__(256)
agg_kernel(const float* __restrict__ x, const int* __restrict__ eidx,
           const int* __restrict__ rowptr, float* __restrict__ rst,
           const float* __restrict__ ca2, const float* __restrict__ cc2,
           const float* __restrict__ ca3, const float* __restrict__ cc3) {
    int node = blockIdx.x * 8 + (threadIdx.x >> 5);
    int lane = threadIdx.x & 31;
    if (node >= NN) return;

    float4 A2, C2, A3, C3;
    if (APPLY_F) {
        A2 = ((const float4*)ca2)[lane];
        C2 = ((const float4*)cc2)[lane];
        A3 = ((const float4*)ca3)[lane];
        C3 = ((const float4*)cc3)[lane];
    }
    const float4* xp = (const float4*)x;

    auto f = [&](float4 v) -> float4 {
        if (APPLY_F) {
            v.x = fmaxf(fmaf(fmaxf(fmaf(v.x, A2.x, C2.x), 0.f), A3.x, C3.x), 0.f);
            v.y = fmaxf(fmaf(fmaxf(fmaf(v.y, A2.y, C2.y), 0.f), A3.y, C3.y), 0.f);
            v.z = fmaxf(fmaf(fmaxf(fmaf(v.z, A2.z, C2.z), 0.f), A3.z, C3.z), 0.f);
            v.w = fmaxf(fmaf(fmaxf(fmaf(v.w, A2.w, C2.w), 0.f), A3.w, C3.w), 0.f);
        }
        return v;
    };

    int s = rowptr[node], e = rowptr[node + 1];
    float4 acc = f(xp[(size_t)node * 32 + lane]);
    int i = s;
    for (; i + 8 <= e; i += 8) {
        int jj[8];
#pragma unroll
        for (int u = 0; u < 8; u++) jj[u] = eidx[i + u];
        float4 v[8];
#pragma unroll
        for (int u = 0; u < 8; u++) v[u] = xp[(size_t)jj[u] * 32 + lane];
#pragma unroll
        for (int u = 0; u < 8; u++) {
            float4 t = f(v[u]);
            acc.x += t.x; acc.y += t.y; acc.z += t.z; acc.w += t.w;
        }
    }
    for (; i < e; i++) {
        float4 t = f(xp[(size_t)eidx[i] * 32 + lane]);
        acc.x += t.x; acc.y += t.y; acc.z += t.z; acc.w += t.w;
    }
    ((float4*)rst)[(size_t)node * 32 + lane] = acc;
}

// ---------------- small utility kernels -------------------------------------
__global__ void zero_stats_kernel(float* __restrict__ s) {
    s[blockIdx.x * 128 + threadIdx.x] = 0.0f;
}

// pre-convert weights: Bt[n][k] = W[k][n], split into bf16 hi + lo
__global__ void convert_w_kernel(const float* __restrict__ W1, const float* __restrict__ W2,
                                 unsigned short* __restrict__ bhi,
                                 unsigned short* __restrict__ blo) {
    int m = blockIdx.y;  // 0..9
    const float* W = (m < 5) ? (W1 + m * 16384) : (W2 + (m - 5) * 16384);
    int e = blockIdx.x * 256 + threadIdx.x;  // 0..16383
    int n = e >> 7, k = e & 127;
    float val = W[k * 128 + n];
    __nv_bfloat16 h = __float2bfloat16(val);
    __nv_bfloat16 l = __float2bfloat16(val - __bfloat162float(h));
    bhi[m * 16384 + n * 128 + k] = __bfloat16_as_ushort(h);
    blo[m * 16384 + n * 128 + k] = __bfloat16_as_ushort(l);
}

// ---------------- HMMA GEMM: out = act(A) @ W + bias, + column stats --------
// bf16x3: D = Ah*Bh + Ah*Bl + Al*Bh, f32 accum, tile 64 rows x 128 cols, K=128.
#define STRD32 68
#define SM_AHI 0
#define SM_ALO (64 * STRD32 * 4)               // 17408
#define SM_BHI (SM_ALO + 64 * STRD32 * 4)      // 34816
#define SM_BLO (SM_BHI + 128 * STRD32 * 4)     // 69632
#define SM_BIAS (SM_BLO + 128 * STRD32 * 4)    // 104448
#define SM_CA (SM_BIAS + 512)
#define SM_CC (SM_CA + 512)
#define SM_STATS (SM_CC + 512)                 // sums[128] + sqs[128]
#define GEMM_SMEM (SM_STATS + 1024)            // 107008 B

template <bool APPLY_BN>
__global__ void __launch_bounds__(256, 2)
gemm_tc_kernel(const float* __restrict__ A,
               const unsigned short* __restrict__ Bhi,
               const unsigned short* __restrict__ Blo,
               const float* __restrict__ bias,
               const float* __restrict__ ca_g, const float* __restrict__ cc_g,
               float* __restrict__ out,
               float* __restrict__ ssum, float* __restrict__ ssq) {
    extern __shared__ char sm[];
    int tid = threadIdx.x;
    int wid = tid >> 5, lane = tid & 31;
    int brow0 = blockIdx.x * 64;

    uint32_t* AHI = (uint32_t*)(sm + SM_AHI);
    uint32_t* ALO = (uint32_t*)(sm + SM_ALO);
    uint32_t* BHI = (uint32_t*)(sm + SM_BHI);
    uint32_t* BLO = (uint32_t*)(sm + SM_BLO);
    float* sums = (float*)(sm + SM_STATS);
    float* sqs = sums + 128;

    // ---- stage B (hi+lo) into smem, restride 64 -> 68 uint32 per row ----
    {
        const uint32_t* s0 = (const uint32_t*)Bhi;
        const uint32_t* s1 = (const uint32_t*)Blo;
#pragma unroll 8
        for (int i = tid; i < 8192; i += 256) {
            int r = i >> 6, kc = i & 63;
            BHI[r * STRD32 + kc] = s0[i];
            BLO[r * STRD32 + kc] = s1[i];
        }
    }
    if (tid < 128) {
        ((float*)(sm + SM_BIAS))[tid] = bias[tid];
        sums[tid] = 0.f;
        sqs[tid] = 0.f;
        if (APPLY_BN) {
            ((float*)(sm + SM_CA))[tid] = ca_g[tid];
            ((float*)(sm + SM_CC))[tid] = cc_g[tid];
        }
    }
    __syncthreads();

    // ---- stage act(A) as bf16 hi/lo in smem (full 128-col rows) ----
    {
        int row = tid >> 2;        // 0..63
        int q = tid & 3;
        int grow = brow0 + row;
        bool valid = grow < NN;
        const float4* ap = (const float4*)(A + (size_t)grow * DD);
        const float* caS = (const float*)(sm + SM_CA);
        const float* ccS = (const float*)(sm + SM_CC);
        uint32_t* ahi = AHI + row * STRD32;
        uint32_t* alo = ALO + row * STRD32;
#pragma unroll
        for (int i = 0; i < 8; i++) {
            int v = q + 4 * i;  // float4 index 0..31
            float4 x = valid ? ap[v] : make_float4(0.f, 0.f, 0.f, 0.f);
            if (APPLY_BN) {
                int k0 = v * 4;
                x.x = fmaxf(fmaf(x.x, caS[k0 + 0], ccS[k0 + 0]), 0.f);
                x.y = fmaxf(fmaf(x.y, caS[k0 + 1], ccS[k0 + 1]), 0.f);
                x.z = fmaxf(fmaf(x.z, caS[k0 + 2], ccS[k0 + 2]), 0.f);
                x.w = fmaxf(fmaf(x.w, caS[k0 + 3], ccS[k0 + 3]), 0.f);
            }
            __nv_bfloat16 hx = __float2bfloat16(x.x);
            __nv_bfloat16 hy = __float2bfloat16(x.y);
            __nv_bfloat16 hz = __float2bfloat16(x.z);
            __nv_bfloat16 hw = __float2bfloat16(x.w);
            ahi[v * 2 + 0] = packbf(hx, hy);
            ahi[v * 2 + 1] = packbf(hz, hw);
            alo[v * 2 + 0] = packbf(__float2bfloat16(x.x - __bfloat162float(hx)),
                                    __float2bfloat16(x.y - __bfloat162float(hy)));
            alo[v * 2 + 1] = packbf(__float2bfloat16(x.z - __bfloat162float(hz)),
                                    __float2bfloat16(x.w - __bfloat162float(hw)));
        }
    }
    __syncthreads();

    // ---- MMA main loop (explicit fragment loads per mma.m16n8k16 spec) ----
    int row0w = (wid & 3) * 16;
    int col0w = (wid >> 2) * 64;
    int g = lane >> 2, t = lane & 3;

    const uint32_t* Ah0p = AHI + (row0w + g) * STRD32 + t;
    const uint32_t* Ah1p = AHI + (row0w + 8 + g) * STRD32 + t;
    const uint32_t* Al0p = ALO + (row0w + g) * STRD32 + t;
    const uint32_t* Al1p = ALO + (row0w + 8 + g) * STRD32 + t;
    const uint32_t* Bhp = BHI + (col0w + g) * STRD32 + t;
    const uint32_t* Blp = BLO + (col0w + g) * STRD32 + t;

    float acc[8][4];
#pragma unroll
    for (int i = 0; i < 8; i++)
#pragma unroll
        for (int j = 0; j < 4; j++) acc[i][j] = 0.f;

#pragma unroll
    for (int ks = 0; ks < 8; ks++) {
        int ko = ks * 8;
        uint32_t ah0 = Ah0p[ko], ah1 = Ah1p[ko], ah2 = Ah0p[ko + 4], ah3 = Ah1p[ko + 4];
        uint32_t al0 = Al0p[ko], al1 = Al1p[ko], al2 = Al0p[ko + 4], al3 = Al1p[ko + 4];
#pragma unroll
        for (int nf = 0; nf < 8; nf++) {
            int bo = ko + nf * 8 * STRD32;
            uint32_t bh0 = Bhp[bo], bh1 = Bhp[bo + 4];
            uint32_t bl0 = Blp[bo], bl1 = Blp[bo + 4];
            MMA_BF16(acc[nf][0], acc[nf][1], acc[nf][2], acc[nf][3],
                     ah0, ah1, ah2, ah3, bh0, bh1);
            MMA_BF16(acc[nf][0], acc[nf][1], acc[nf][2], acc[nf][3],
                     ah0, ah1, ah2, ah3, bl0, bl1);
            MMA_BF16(acc[nf][0], acc[nf][1], acc[nf][2], acc[nf][3],
                     al0, al1, al2, al3, bh0, bh1);
        }
    }

    // ---- epilogue: + bias, store, column stats ----
    {
        int grow0 = brow0 + row0w + g;
        int grow1 = grow0 + 8;
        bool ok0 = grow0 < NN, ok1 = grow1 < NN;
        const float* bS = (const float*)(sm + SM_BIAS);
#pragma unroll
        for (int nf = 0; nf < 8; nf++) {
            int c = col0w + nf * 8 + 2 * t;
            float bx = bS[c], by = bS[c + 1];
            float a0 = acc[nf][0] + bx, a1 = acc[nf][1] + by;
            float a2 = acc[nf][2] + bx, a3 = acc[nf][3] + by;
            if (ok0)
                *(float2*)(out + (size_t)grow0 * DD + c) = make_float2(a0, a1);
            if (ok1)
                *(float2*)(out + (size_t)grow1 * DD + c) = make_float2(a2, a3);
            float s0 = (ok0 ? a0 : 0.f) + (ok1 ? a2 : 0.f);
            float s1 = (ok0 ? a1 : 0.f) + (ok1 ? a3 : 0.f);
            float q0 = (ok0 ? a0 * a0 : 0.f) + (ok1 ? a2 * a2 : 0.f);
            float q1 = (ok0 ? a1 * a1 : 0.f) + (ok1 ? a3 * a3 : 0.f);
#pragma unroll
            for (int m = 16; m >= 4; m >>= 1) {
                s0 += __shfl_xor_sync(0xffffffffu, s0, m);
                s1 += __shfl_xor_sync(0xffffffffu, s1, m);
                q0 += __shfl_xor_sync(0xffffffffu, q0, m);
                q1 += __shfl_xor_sync(0xffffffffu, q1, m);
            }
            if (lane < 4) {
                atomicAdd(&sums[c], s0);
                atomicAdd(&sums[c + 1], s1);
                atomicAdd(&sqs[c], q0);
                atomicAdd(&sqs[c + 1], q1);
            }
        }
    }
    __syncthreads();
    if (tid < 128) {
        atomicAdd(ssum + tid, sums[tid]);
        atomicAdd(ssq + tid, sqs[tid]);
    }
}

// ---------------- finalize BN coefficients ----------------------------------
__global__ void finalize_kernel(const float* __restrict__ ssum, const float* __restrict__ ssq,
                                const float* __restrict__ g, const float* __restrict__ b,
                                float* __restrict__ ca, float* __restrict__ cc) {
    int c = threadIdx.x;
    float m = ssum[c] * (1.0f / NN);
    float var = ssq[c] * (1.0f / NN) - m * m;
    float inv = rsqrtf(var + 1e-5f);
    float a = g[c] * inv;
    ca[c] = a;
    cc[c] = b[c] - m * a;
}

// ---------------- stats of y = relu(a2*x2 + c2) (no y write) ----------------
__global__ void ystats_kernel(const float* __restrict__ x,
                              const float* __restrict__ ca, const float* __restrict__ cc,
                              float* __restrict__ ssum, float* __restrict__ ssq) {
    int c = threadIdx.x;
    float a = ca[c];
    float off = cc[c];
    int r0 = blockIdx.x * 64;
    float s = 0.f, q = 0.f;
#pragma unroll 4
    for (int i = 0; i < 64; i++) {
        int r = r0 + i;
        if (r < NN) {
            float v = fmaxf(fmaf(x[(size_t)r * DD + c], a, off), 0.f);
            s += v;
            q += v * v;
        }
    }
    atomicAdd(ssum + c, s);
    atomicAdd(ssq + c, q);
}

// ---------------- out = relu(a3*relu(a2*x2+c2) + c3) (final layer only) -----
__global__ void final_apply_kernel(const float* __restrict__ x, float* __restrict__ outp,
                                   const float* __restrict__ ca2, const float* __restrict__ cc2,
                                   const float* __restrict__ ca3, const float* __restrict__ cc3) {
    int idx = blockIdx.x * blockDim.x + threadIdx.x;
    if (idx < NVEC4) {
        float4 v = ((const float4*)x)[idx];
        int c0 = (idx * 4) & (DD - 1);
        v.x = fmaxf(fmaf(v.x, ca2[c0 + 0], cc2[c0 + 0]), 0.f);
        v.y = fmaxf(fmaf(v.y, ca2[c0 + 1], cc2[c0 + 1]), 0.f);
        v.z = fmaxf(fmaf(v.z, ca2[c0 + 2], cc2[c0 + 2]), 0.f);
        v.w = fmaxf(fmaf(v.w, ca2[c0 + 3], cc2[c0 + 3]), 0.f);
        v.x = fmaxf(fmaf(v.x, ca3[c0 + 0], cc3[c0 + 0]), 0.f);
        v.y = fmaxf(fmaf(v.y, ca3[c0 + 1], cc3[c0 + 1]), 0.f);
        v.z = fmaxf(fmaf(v.z, ca3[c0 + 2], cc3[c0 + 2]), 0.f);
        v.w = fmaxf(fmaf(v.w, ca3[c0 + 3], cc3[c0 + 3]), 0.f);
        ((float4*)outp)[idx] = v;
    }
}

// ---------------- launch ----------------------------------------------------
extern "C" void kernel_launch(void* const* d_in, const int* in_sizes, int n_in,
                              void* d_out, int out_size) {
    const float* h_in = (const float*)d_in[0];
    const int* src = (const int*)d_in[1];
    const int* dst = (const int*)d_in[2];
    const float* W1 = (const float*)d_in[3];
    const float* b1 = (const float*)d_in[4];
    const float* W2 = (const float*)d_in[5];
    const float* b2 = (const float*)d_in[6];
    const float* bn1g = (const float*)d_in[7];
    const float* bn1b = (const float*)d_in[8];
    const float* bn2g = (const float*)d_in[9];
    const float* bn2b = (const float*)d_in[10];
    const float* bn3g = (const float*)d_in[11];
    const float* bn3b = (const float*)d_in[12];
    int E = in_sizes[1];
    if (E > EMAX) E = EMAX;

    float *rst, *x1, *x2, *stats, *coef;
    unsigned short *bhi, *blo;
    int *deg, *rowptr, *cur, *eidx, *bsum, *bscan;
    cudaGetSymbolAddress((void**)&rst, g_rst);
    cudaGetSymbolAddress((void**)&x1, g_x1);
    cudaGetSymbolAddress((void**)&x2, g_x2);
    cudaGetSymbolAddress((void**)&stats, g_stats);
    cudaGetSymbolAddress((void**)&coef, g_coef);
    cudaGetSymbolAddress((void**)&bhi, g_Bhi);
    cudaGetSymbolAddress((void**)&blo, g_Blo);
    cudaGetSymbolAddress((void**)&deg, g_deg);
    cudaGetSymbolAddress((void**)&rowptr, g_rowptr);
    cudaGetSymbolAddress((void**)&cur, g_cur);
    cudaGetSymbolAddress((void**)&eidx, g_eidx);
    cudaGetSymbolAddress((void**)&bsum, g_bsum);
    cudaGetSymbolAddress((void**)&bscan, g_bscan);

    cudaFuncSetAttribute((const void*)gemm_tc_kernel<false>,
                         cudaFuncAttributeMaxDynamicSharedMemorySize, GEMM_SMEM);
    cudaFuncSetAttribute((const void*)gemm_tc_kernel<true>,
                         cudaFuncAttributeMaxDynamicSharedMemorySize, GEMM_SMEM);

    const int row_blocks = (NN + 63) / 64;       // 782
    const int vec_blocks = (NVEC4 + 255) / 256;  // 6250
    const int e_blocks = (E + 255) / 256;
    const int agg_blocks = (NN + 7) / 8;

    // ---- setup: weight conversion + CSR build ----
    convert_w_kernel<<<dim3(64, 10), 256>>>(W1, W2, bhi, blo);
    zero_deg_kernel<<<NB, 256>>>(deg);
    count_deg_kernel<<<e_blocks, 256>>>(dst, deg, E);
    scanA_kernel<<<NB, 256>>>(deg, rowptr, bsum);
    scanB_kernel<<<1, 256>>>(bsum, bscan, rowptr);
    scanC_kernel<<<NB, 256>>>(rowptr, bscan, cur);
    scatter_kernel<<<e_blocks, 256>>>(src, dst, cur, eidx, E);

    for (int l = 0; l < LAYERS; l++) {
        zero_stats_kernel<<<6, 128>>>(stats);
        // aggregation: layer 0 reads h_in plain; layers 1+ read x2 of previous
        // layer with the bn2->bn3 elementwise chain fused into the gather.
        if (l == 0) {
            agg_kernel<false><<<agg_blocks, 256>>>(h_in, eidx, rowptr, rst,
                                                   nullptr, nullptr, nullptr, nullptr);
        } else {
            agg_kernel<true><<<agg_blocks, 256>>>(x2, eidx, rowptr, rst,
                                                  coef + 2 * DD, coef + 3 * DD,
                                                  coef + 4 * DD, coef + 5 * DD);
        }

        // x1 = rst @ W1 + b1 (+ stats1 fused)
        gemm_tc_kernel<false><<<row_blocks, 256, GEMM_SMEM>>>(
            rst, bhi + l * 16384, blo + l * 16384, b1 + l * DD, nullptr, nullptr,
            x1, stats + 0 * DD, stats + 1 * DD);
        finalize_kernel<<<1, 128>>>(stats + 0 * DD, stats + 1 * DD,
                                    bn1g + l * DD, bn1b + l * DD,
                                    coef + 0 * DD, coef + 1 * DD);

        // x2 = relu(bn1(x1)) @ W2 + b2 (BN1 fused into A conversion, + stats2)
        gemm_tc_kernel<true><<<row_blocks, 256, GEMM_SMEM>>>(
            x1, bhi + (5 + l) * 16384, blo + (5 + l) * 16384, b2 + l * DD,
            coef + 0 * DD, coef + 1 * DD, x2, stats + 2 * DD, stats + 3 * DD);
        finalize_kernel<<<1, 128>>>(stats + 2 * DD, stats + 3 * DD,
                                    bn2g + l * DD, bn2b + l * DD,
                                    coef + 2 * DD, coef + 3 * DD);

        // stats of y = relu(bn2(x2)) computed on the fly
        ystats_kernel<<<row_blocks, 128>>>(x2, coef + 2 * DD, coef + 3 * DD,
                                           stats + 4 * DD, stats + 5 * DD);
        finalize_kernel<<<1, 128>>>(stats + 4 * DD, stats + 5 * DD,
                                    bn3g + l * DD, bn3b + l * DD,
                                    coef + 4 * DD, coef + 5 * DD);
    }

    // final output: h = relu(bn3(relu(bn2(x2)))) of the last layer
    final_apply_kernel<<<vec_blocks, 256>>>(x2, (float*)d_out,
                                            coef + 2 * DD, coef + 3 * DD,
                                            coef + 4 * DD, coef + 5 * DD);
}

// round 15
// speedup vs baseline: 1.2442x; 1.0659x over previous
#include <cuda_runtime.h>
#include <cuda_bf16.h>
#include <cstdint>

#define NN 50000
#define DD 128
#define LAYERS 5
#define NVEC4 (NN * DD / 4)
#define NB ((NN + 255) / 256)          // 196 scan blocks
#define EMAX 1000000
#define TILES ((NN + 63) / 64)         // 782
#define GEMM_GRID 296                  // persistent-style grid, ~2.6 tiles/block

// ---------------- scratch (static device allocations; no cudaMalloc) --------
__device__ float g_rst[NN * DD];
__device__ float g_x1[NN * DD];
__device__ float g_x2[NN * DD];
__device__ float g_stats[6 * DD];
__device__ float g_coef[6 * DD];
__device__ int g_deg[NN];
__device__ int g_rowptr[NN + 1];
__device__ int g_cur[NN];
__device__ int g_eidx[EMAX];
__device__ int g_bsum[NB];
__device__ int g_bscan[NB];
// pre-converted weights: 10 matrices (5x W1, 5x W2), Bt[n][k] = W[k][n], bf16 hi/lo
__device__ unsigned short g_Bhi[10 * 16384];
__device__ unsigned short g_Blo[10 * 16384];

// ---------------- helpers ----------------------------------------------------
__device__ __forceinline__ uint32_t packbf(__nv_bfloat16 lo16, __nv_bfloat16 hi16) {
    return (uint32_t)__bfloat16_as_ushort(lo16) |
           ((uint32_t)__bfloat16_as_ushort(hi16) << 16);
}

#define MMA_BF16(d0, d1, d2, d3, a0, a1, a2, a3, b0, b1) \
    asm volatile("mma.sync.aligned.m16n8k16.row.col.f32.bf16.bf16.f32 " \
                 "{%0,%1,%2,%3}, {%4,%5,%6,%7}, {%8,%9}, {%0,%1,%2,%3};" \
                 : "+f"(d0), "+f"(d1), "+f"(d2), "+f"(d3) \
                 : "r"(a0), "r"(a1), "r"(a2), "r"(a3), "r"(b0), "r"(b1))

// ---------------- CSR build --------------------------------------------------
__global__ void zero_deg_kernel(int* __restrict__ deg) {
    int i = blockIdx.x * 256 + threadIdx.x;
    if (i < NN) deg[i] = 0;
}
__global__ void count_deg_kernel(const int* __restrict__ dst, int* __restrict__ deg, int E) {
    int e = blockIdx.x * 256 + threadIdx.x;
    if (e < E) atomicAdd(&deg[dst[e]], 1);
}
__global__ void scanA_kernel(const int* __restrict__ deg, int* __restrict__ rowptr,
                             int* __restrict__ bsum) {
    __shared__ int ssc[256];
    int tid = threadIdx.x;
    int idx = blockIdx.x * 256 + tid;
    int val = (idx < NN) ? deg[idx] : 0;
    ssc[tid] = val;
    __syncthreads();
#pragma unroll
    for (int off = 1; off < 256; off <<= 1) {
        int t = (tid >= off) ? ssc[tid - off] : 0;
        __syncthreads();
        ssc[tid] += t;
        __syncthreads();
    }
    if (idx < NN) rowptr[idx] = ssc[tid] - val;  // exclusive
    if (tid == 255) bsum[blockIdx.x] = ssc[255];
}
__global__ void scanB_kernel(const int* __restrict__ bsum, int* __restrict__ bscan,
                             int* __restrict__ rowptr) {
    __shared__ int ssc[256];
    int tid = threadIdx.x;
    int val = (tid < NB) ? bsum[tid] : 0;
    ssc[tid] = val;
    __syncthreads();
#pragma unroll
    for (int off = 1; off < 256; off <<= 1) {
        int t = (tid >= off) ? ssc[tid - off] : 0;
        __syncthreads();
        ssc[tid] += t;
        __syncthreads();
    }
    if (tid < NB) bscan[tid] = ssc[tid] - val;  // exclusive
    if (tid == 255) rowptr[NN] = ssc[255];
}
__global__ void scanC_kernel(int* __restrict__ rowptr, const int* __restrict__ bscan,
                             int* __restrict__ cur) {
    int i = blockIdx.x * 256 + threadIdx.x;
    if (i < NN) {
        int v = rowptr[i] + bscan[blockIdx.x];
        rowptr[i] = v;
        cur[i] = v;
    }
}
__global__ void scatter_kernel(const int* __restrict__ src, const int* __restrict__ dst,
                               int* __restrict__ cur, int* __restrict__ eidx, int E) {
    int e = blockIdx.x * 256 + threadIdx.x;
    if (e < E) {
        int p = atomicAdd(&cur[dst[e]], 1);
        eidx[p] = src[e];
    }
}

// ---------------- aggregation ------------------------------------------------
// rst[i] = f(x[i]) + sum_{j in adj(i)} f(x[j])
// APPLY_F: f(v) = relu(a3*relu(a2*v + c2) + c3); otherwise identity.
template <bool APPLY_F>
__global__ void __launch_bounds__(256)
agg_kernel(const float* __restrict__ x, const int* __restrict__ eidx,
           const int* __restrict__ rowptr, float* __restrict__ rst,
           const float* __restrict__ ca2, const float* __restrict__ cc2,
           const float* __restrict__ ca3, const float* __restrict__ cc3) {
    int node = blockIdx.x * 8 + (threadIdx.x >> 5);
    int lane = threadIdx.x & 31;
    if (node >= NN) return;

    float4 A2, C2, A3, C3;
    if (APPLY_F) {
        A2 = ((const float4*)ca2)[lane];
        C2 = ((const float4*)cc2)[lane];
        A3 = ((const float4*)ca3)[lane];
        C3 = ((const float4*)cc3)[lane];
    }
    const float4* xp = (const float4*)x;

    auto f = [&](float4 v) -> float4 {
        if (APPLY_F) {
            v.x = fmaxf(fmaf(fmaxf(fmaf(v.x, A2.x, C2.x), 0.f), A3.x, C3.x), 0.f);
            v.y = fmaxf(fmaf(fmaxf(fmaf(v.y, A2.y, C2.y), 0.f), A3.y, C3.y), 0.f);
            v.z = fmaxf(fmaf(fmaxf(fmaf(v.z, A2.z, C2.z), 0.f), A3.z, C3.z), 0.f);
            v.w = fmaxf(fmaf(fmaxf(fmaf(v.w, A2.w, C2.w), 0.f), A3.w, C3.w), 0.f);
        }
        return v;
    };

    int s = rowptr[node], e = rowptr[node + 1];
    float4 acc = f(xp[(size_t)node * 32 + lane]);
    int i = s;
    for (; i + 8 <= e; i += 8) {
        int jj[8];
#pragma unroll
        for (int u = 0; u < 8; u++) jj[u] = eidx[i + u];
        float4 v[8];
#pragma unroll
        for (int u = 0; u < 8; u++) v[u] = xp[(size_t)jj[u] * 32 + lane];
#pragma unroll
        for (int u = 0; u < 8; u++) {
            float4 t = f(v[u]);
            acc.x += t.x; acc.y += t.y; acc.z += t.z; acc.w += t.w;
        }
    }
    for (; i < e; i++) {
        float4 t = f(xp[(size_t)eidx[i] * 32 + lane]);
        acc.x += t.x; acc.y += t.y; acc.z += t.z; acc.w += t.w;
    }
    ((float4*)rst)[(size_t)node * 32 + lane] = acc;
}

// ---------------- small utility kernels -------------------------------------
__global__ void zero_stats_kernel(float* __restrict__ s) {
    s[blockIdx.x * 128 + threadIdx.x] = 0.0f;
}

// pre-convert weights: Bt[n][k] = W[k][n], split into bf16 hi + lo
__global__ void convert_w_kernel(const float* __restrict__ W1, const float* __restrict__ W2,
                                 unsigned short* __restrict__ bhi,
                                 unsigned short* __restrict__ blo) {
    int m = blockIdx.y;  // 0..9
    const float* W = (m < 5) ? (W1 + m * 16384) : (W2 + (m - 5) * 16384);
    int e = blockIdx.x * 256 + threadIdx.x;  // 0..16383
    int n = e >> 7, k = e & 127;
    float val = W[k * 128 + n];
    __nv_bfloat16 h = __float2bfloat16(val);
    __nv_bfloat16 l = __float2bfloat16(val - __bfloat162float(h));
    bhi[m * 16384 + n * 128 + k] = __bfloat16_as_ushort(h);
    blo[m * 16384 + n * 128 + k] = __bfloat16_as_ushort(l);
}

// ---------------- HMMA GEMM: out = act(A) @ W + bias, + column stats --------
// bf16x3: D = Ah*Bh + Ah*Bl + Al*Bh, f32 accum, tile 64 rows x 128 cols, K=128.
// Persistent-style grid: each block stages W ONCE and loops over its tiles;
// block-level column stats accumulate in smem and flush to global once.
#define STRD32 68
#define SM_AHI 0
#define SM_ALO (64 * STRD32 * 4)               // 17408
#define SM_BHI (SM_ALO + 64 * STRD32 * 4)      // 34816
#define SM_BLO (SM_BHI + 128 * STRD32 * 4)     // 69632
#define SM_BIAS (SM_BLO + 128 * STRD32 * 4)    // 104448
#define SM_CA (SM_BIAS + 512)
#define SM_CC (SM_CA + 512)
#define SM_STATS (SM_CC + 512)                 // sums[128] + sqs[128]
#define GEMM_SMEM (SM_STATS + 1024)            // 107008 B

template <bool APPLY_BN>
__global__ void __launch_bounds__(256, 2)
gemm_tc_kernel(const float* __restrict__ A,
               const unsigned short* __restrict__ Bhi,
               const unsigned short* __restrict__ Blo,
               const float* __restrict__ bias,
               const float* __restrict__ ca_g, const float* __restrict__ cc_g,
               float* __restrict__ out,
               float* __restrict__ ssum, float* __restrict__ ssq) {
    extern __shared__ char sm[];
    int tid = threadIdx.x;
    int wid = tid >> 5, lane = tid & 31;

    uint32_t* AHI = (uint32_t*)(sm + SM_AHI);
    uint32_t* ALO = (uint32_t*)(sm + SM_ALO);
    uint32_t* BHI = (uint32_t*)(sm + SM_BHI);
    uint32_t* BLO = (uint32_t*)(sm + SM_BLO);
    float* sums = (float*)(sm + SM_STATS);
    float* sqs = sums + 128;

    // ---- stage B (hi+lo) into smem ONCE, restride 64 -> 68 uint32 per row ----
    {
        const uint32_t* s0 = (const uint32_t*)Bhi;
        const uint32_t* s1 = (const uint32_t*)Blo;
#pragma unroll 8
        for (int i = tid; i < 8192; i += 256) {
            int r = i >> 6, kc = i & 63;
            BHI[r * STRD32 + kc] = s0[i];
            BLO[r * STRD32 + kc] = s1[i];
        }
    }
    if (tid < 128) {
        ((float*)(sm + SM_BIAS))[tid] = bias[tid];
        sums[tid] = 0.f;
        sqs[tid] = 0.f;
        if (APPLY_BN) {
            ((float*)(sm + SM_CA))[tid] = ca_g[tid];
            ((float*)(sm + SM_CC))[tid] = cc_g[tid];
        }
    }
    __syncthreads();

    int row0w = (wid & 3) * 16;
    int col0w = (wid >> 2) * 64;
    int g = lane >> 2, t = lane & 3;

    for (int tile = blockIdx.x; tile < TILES; tile += GEMM_GRID) {
        int brow0 = tile * 64;

        // ---- stage act(A) as bf16 hi/lo in smem (full 128-col rows) ----
        {
            int row = tid >> 2;        // 0..63
            int q = tid & 3;
            int grow = brow0 + row;
            bool valid = grow < NN;
            const float4* ap = (const float4*)(A + (size_t)grow * DD);
            const float* caS = (const float*)(sm + SM_CA);
            const float* ccS = (const float*)(sm + SM_CC);
            uint32_t* ahi = AHI + row * STRD32;
            uint32_t* alo = ALO + row * STRD32;
#pragma unroll
            for (int i = 0; i < 8; i++) {
                int v = q + 4 * i;  // float4 index 0..31
                float4 x = valid ? ap[v] : make_float4(0.f, 0.f, 0.f, 0.f);
                if (APPLY_BN) {
                    int k0 = v * 4;
                    x.x = fmaxf(fmaf(x.x, caS[k0 + 0], ccS[k0 + 0]), 0.f);
                    x.y = fmaxf(fmaf(x.y, caS[k0 + 1], ccS[k0 + 1]), 0.f);
                    x.z = fmaxf(fmaf(x.z, caS[k0 + 2], ccS[k0 + 2]), 0.f);
                    x.w = fmaxf(fmaf(x.w, caS[k0 + 3], ccS[k0 + 3]), 0.f);
                }
                __nv_bfloat16 hx = __float2bfloat16(x.x);
                __nv_bfloat16 hy = __float2bfloat16(x.y);
                __nv_bfloat16 hz = __float2bfloat16(x.z);
                __nv_bfloat16 hw = __float2bfloat16(x.w);
                ahi[v * 2 + 0] = packbf(hx, hy);
                ahi[v * 2 + 1] = packbf(hz, hw);
                alo[v * 2 + 0] = packbf(__float2bfloat16(x.x - __bfloat162float(hx)),
                                        __float2bfloat16(x.y - __bfloat162float(hy)));
                alo[v * 2 + 1] = packbf(__float2bfloat16(x.z - __bfloat162float(hz)),
                                        __float2bfloat16(x.w - __bfloat162float(hw)));
            }
        }
        __syncthreads();

        // ---- MMA main loop (explicit fragment loads per mma.m16n8k16 spec) ----
        const uint32_t* Ah0p = AHI + (row0w + g) * STRD32 + t;
        const uint32_t* Ah1p = AHI + (row0w + 8 + g) * STRD32 + t;
        const uint32_t* Al0p = ALO + (row0w + g) * STRD32 + t;
        const uint32_t* Al1p = ALO + (row0w + 8 + g) * STRD32 + t;
        const uint32_t* Bhp = BHI + (col0w + g) * STRD32 + t;
        const uint32_t* Blp = BLO + (col0w + g) * STRD32 + t;

        float acc[8][4];
#pragma unroll
        for (int i = 0; i < 8; i++)
#pragma unroll
            for (int j = 0; j < 4; j++) acc[i][j] = 0.f;

#pragma unroll
        for (int ks = 0; ks < 8; ks++) {
            int ko = ks * 8;
            uint32_t ah0 = Ah0p[ko], ah1 = Ah1p[ko], ah2 = Ah0p[ko + 4], ah3 = Ah1p[ko + 4];
            uint32_t al0 = Al0p[ko], al1 = Al1p[ko], al2 = Al0p[ko + 4], al3 = Al1p[ko + 4];
#pragma unroll
            for (int nf = 0; nf < 8; nf++) {
                int bo = ko + nf * 8 * STRD32;
                uint32_t bh0 = Bhp[bo], bh1 = Bhp[bo + 4];
                uint32_t bl0 = Blp[bo], bl1 = Blp[bo + 4];
                MMA_BF16(acc[nf][0], acc[nf][1], acc[nf][2], acc[nf][3],
                         ah0, ah1, ah2, ah3, bh0, bh1);
                MMA_BF16(acc[nf][0], acc[nf][1], acc[nf][2], acc[nf][3],
                         ah0, ah1, ah2, ah3, bl0, bl1);
                MMA_BF16(acc[nf][0], acc[nf][1], acc[nf][2], acc[nf][3],
                         al0, al1, al2, al3, bh0, bh1);
            }
        }

        // ---- epilogue: + bias, store, column stats into smem ----
        {
            int grow0 = brow0 + row0w + g;
            int grow1 = grow0 + 8;
            bool ok0 = grow0 < NN, ok1 = grow1 < NN;
            const float* bS = (const float*)(sm + SM_BIAS);
#pragma unroll
            for (int nf = 0; nf < 8; nf++) {
                int c = col0w + nf * 8 + 2 * t;
                float bx = bS[c], by = bS[c + 1];
                float a0 = acc[nf][0] + bx, a1 = acc[nf][1] + by;
                float a2 = acc[nf][2] + bx, a3 = acc[nf][3] + by;
                if (ok0)
                    *(float2*)(out + (size_t)grow0 * DD + c) = make_float2(a0, a1);
                if (ok1)
                    *(float2*)(out + (size_t)grow1 * DD + c) = make_float2(a2, a3);
                float s0 = (ok0 ? a0 : 0.f) + (ok1 ? a2 : 0.f);
                float s1 = (ok0 ? a1 : 0.f) + (ok1 ? a3 : 0.f);
                float q0 = (ok0 ? a0 * a0 : 0.f) + (ok1 ? a2 * a2 : 0.f);
                float q1 = (ok0 ? a1 * a1 : 0.f) + (ok1 ? a3 * a3 : 0.f);
#pragma unroll
                for (int m = 16; m >= 4; m >>= 1) {
                    s0 += __shfl_xor_sync(0xffffffffu, s0, m);
                    s1 += __shfl_xor_sync(0xffffffffu, s1, m);
                    q0 += __shfl_xor_sync(0xffffffffu, q0, m);
                    q1 += __shfl_xor_sync(0xffffffffu, q1, m);
                }
                if (lane < 4) {
                    atomicAdd(&sums[c], s0);
                    atomicAdd(&sums[c + 1], s1);
                    atomicAdd(&sqs[c], q0);
                    atomicAdd(&sqs[c + 1], q1);
                }
            }
        }
        __syncthreads();   // A smem fully consumed before next tile restages
    }

    // ---- one global stats flush per block ----
    if (tid < 128) {
        atomicAdd(ssum + tid, sums[tid]);
        atomicAdd(ssq + tid, sqs[tid]);
    }
}

// ---------------- finalize BN coefficients ----------------------------------
__global__ void finalize_kernel(const float* __restrict__ ssum, const float* __restrict__ ssq,
                                const float* __restrict__ g, const float* __restrict__ b,
                                float* __restrict__ ca, float* __restrict__ cc) {
    int c = threadIdx.x;
    float m = ssum[c] * (1.0f / NN);
    float var = ssq[c] * (1.0f / NN) - m * m;
    float inv = rsqrtf(var + 1e-5f);
    float a = g[c] * inv;
    ca[c] = a;
    cc[c] = b[c] - m * a;
}

// ---------------- stats of y = relu(a2*x2 + c2) (no y write) ----------------
__global__ void ystats_kernel(const float* __restrict__ x,
                              const float* __restrict__ ca, const float* __restrict__ cc,
                              float* __restrict__ ssum, float* __restrict__ ssq) {
    int c = threadIdx.x;
    float a = ca[c];
    float off = cc[c];
    int r0 = blockIdx.x * 64;
    float s = 0.f, q = 0.f;
#pragma unroll 4
    for (int i = 0; i < 64; i++) {
        int r = r0 + i;
        if (r < NN) {
            float v = fmaxf(fmaf(x[(size_t)r * DD + c], a, off), 0.f);
            s += v;
            q += v * v;
        }
    }
    atomicAdd(ssum + c, s);
    atomicAdd(ssq + c, q);
}

// ---------------- out = relu(a3*relu(a2*x2+c2) + c3) (final layer only) -----
__global__ void final_apply_kernel(const float* __restrict__ x, float* __restrict__ outp,
                                   const float* __restrict__ ca2, const float* __restrict__ cc2,
                                   const float* __restrict__ ca3, const float* __restrict__ cc3) {
    int idx = blockIdx.x * blockDim.x + threadIdx.x;
    if (idx < NVEC4) {
        float4 v = ((const float4*)x)[idx];
        int c0 = (idx * 4) & (DD - 1);
        v.x = fmaxf(fmaf(v.x, ca2[c0 + 0], cc2[c0 + 0]), 0.f);
        v.y = fmaxf(fmaf(v.y, ca2[c0 + 1], cc2[c0 + 1]), 0.f);
        v.z = fmaxf(fmaf(v.z, ca2[c0 + 2], cc2[c0 + 2]), 0.f);
        v.w = fmaxf(fmaf(v.w, ca2[c0 + 3], cc2[c0 + 3]), 0.f);
        v.x = fmaxf(fmaf(v.x, ca3[c0 + 0], cc3[c0 + 0]), 0.f);
        v.y = fmaxf(fmaf(v.y, ca3[c0 + 1], cc3[c0 + 1]), 0.f);
        v.z = fmaxf(fmaf(v.z, ca3[c0 + 2], cc3[c0 + 2]), 0.f);
        v.w = fmaxf(fmaf(v.w, ca3[c0 + 3], cc3[c0 + 3]), 0.f);
        ((float4*)outp)[idx] = v;
    }
}

// ---------------- launch ----------------------------------------------------
extern "C" void kernel_launch(void* const* d_in, const int* in_sizes, int n_in,
                              void* d_out, int out_size) {
    const float* h_in = (const float*)d_in[0];
    const int* src = (const int*)d_in[1];
    const int* dst = (const int*)d_in[2];
    const float* W1 = (const float*)d_in[3];
    const float* b1 = (const float*)d_in[4];
    const float* W2 = (const float*)d_in[5];
    const float* b2 = (const float*)d_in[6];
    const float* bn1g = (const float*)d_in[7];
    const float* bn1b = (const float*)d_in[8];
    const float* bn2g = (const float*)d_in[9];
    const float* bn2b = (const float*)d_in[10];
    const float* bn3g = (const float*)d_in[11];
    const float* bn3b = (const float*)d_in[12];
    int E = in_sizes[1];
    if (E > EMAX) E = EMAX;

    float *rst, *x1, *x2, *stats, *coef;
    unsigned short *bhi, *blo;
    int *deg, *rowptr, *cur, *eidx, *bsum, *bscan;
    cudaGetSymbolAddress((void**)&rst, g_rst);
    cudaGetSymbolAddress((void**)&x1, g_x1);
    cudaGetSymbolAddress((void**)&x2, g_x2);
    cudaGetSymbolAddress((void**)&stats, g_stats);
    cudaGetSymbolAddress((void**)&coef, g_coef);
    cudaGetSymbolAddress((void**)&bhi, g_Bhi);
    cudaGetSymbolAddress((void**)&blo, g_Blo);
    cudaGetSymbolAddress((void**)&deg, g_deg);
    cudaGetSymbolAddress((void**)&rowptr, g_rowptr);
    cudaGetSymbolAddress((void**)&cur, g_cur);
    cudaGetSymbolAddress((void**)&eidx, g_eidx);
    cudaGetSymbolAddress((void**)&bsum, g_bsum);
    cudaGetSymbolAddress((void**)&bscan, g_bscan);

    cudaFuncSetAttribute((const void*)gemm_tc_kernel<false>,
                         cudaFuncAttributeMaxDynamicSharedMemorySize, GEMM_SMEM);
    cudaFuncSetAttribute((const void*)gemm_tc_kernel<true>,
                         cudaFuncAttributeMaxDynamicSharedMemorySize, GEMM_SMEM);

    const int row_blocks = (NN + 63) / 64;       // 782 (ystats)
    const int vec_blocks = (NVEC4 + 255) / 256;  // 6250
    const int e_blocks = (E + 255) / 256;
    const int agg_blocks = (NN + 7) / 8;

    // ---- setup: weight conversion + CSR build ----
    convert_w_kernel<<<dim3(64, 10), 256>>>(W1, W2, bhi, blo);
    zero_deg_kernel<<<NB, 256>>>(deg);
    count_deg_kernel<<<e_blocks, 256>>>(dst, deg, E);
    scanA_kernel<<<NB, 256>>>(deg, rowptr, bsum);
    scanB_kernel<<<1, 256>>>(bsum, bscan, rowptr);
    scanC_kernel<<<NB, 256>>>(rowptr, bscan, cur);
    scatter_kernel<<<e_blocks, 256>>>(src, dst, cur, eidx, E);

    for (int l = 0; l < LAYERS; l++) {
        zero_stats_kernel<<<6, 128>>>(stats);
        // aggregation: layer 0 reads h_in plain; layers 1+ read x2 of previous
        // layer with the bn2->bn3 elementwise chain fused into the gather.
        if (l == 0) {
            agg_kernel<false><<<agg_blocks, 256>>>(h_in, eidx, rowptr, rst,
                                                   nullptr, nullptr, nullptr, nullptr);
        } else {
            agg_kernel<true><<<agg_blocks, 256>>>(x2, eidx, rowptr, rst,
                                                  coef + 2 * DD, coef + 3 * DD,
                                                  coef + 4 * DD, coef + 5 * DD);
        }

        // x1 = rst @ W1 + b1 (+ stats1 fused)
        gemm_tc_kernel<false><<<GEMM_GRID, 256, GEMM_SMEM>>>(
            rst, bhi + l * 16384, blo + l * 16384, b1 + l * DD, nullptr, nullptr,
            x1, stats + 0 * DD, stats + 1 * DD);
        finalize_kernel<<<1, 128>>>(stats + 0 * DD, stats + 1 * DD,
                                    bn1g + l * DD, bn1b + l * DD,
                                    coef + 0 * DD, coef + 1 * DD);

        // x2 = relu(bn1(x1)) @ W2 + b2 (BN1 fused into A conversion, + stats2)
        gemm_tc_kernel<true><<<GEMM_GRID, 256, GEMM_SMEM>>>(
            x1, bhi + (5 + l) * 16384, blo + (5 + l) * 16384, b2 + l * DD,
            coef + 0 * DD, coef + 1 * DD, x2, stats + 2 * DD, stats + 3 * DD);
        finalize_kernel<<<1, 128>>>(stats + 2 * DD, stats + 3 * DD,
                                    bn2g + l * DD, bn2b + l * DD,
                                    coef + 2 * DD, coef + 3 * DD);

        // stats of y = relu(bn2(x2)) computed on the fly
        ystats_kernel<<<row_blocks, 128>>>(x2, coef + 2 * DD, coef + 3 * DD,
                                           stats + 4 * DD, stats + 5 * DD);
        finalize_kernel<<<1, 128>>>(stats + 4 * DD, stats + 5 * DD,
                                    bn3g + l * DD, bn3b + l * DD,
                                    coef + 4 * DD, coef + 5 * DD);
    }

    // final output: h = relu(bn3(relu(bn2(x2)))) of the last layer
    final_apply_kernel<<<vec_blocks, 256>>>(x2, (float*)d_out,
                                            coef + 2 * DD, coef + 3 * DD,
                                            coef + 4 * DD, coef + 5 * DD);
}